// round 6
// baseline (speedup 1.0000x reference)
#include <cuda_runtime.h>
#include <math.h>

#define C_DT    0.01f
#define C_STEPS 100
#define C_NOSC  50
#define C_NPER  50
#define C_LIM   1.0471975511965976f   /* pi/3 */
#define C_MGL2  4.905f                /* m*g*(l/2), I = 1 */
#define NBP     13                    /* producer blocks: 4 oscillators each (52, 2 padded) */

__device__ __align__(128) float g_tq[C_STEPS * 32];  // [step][producer block]
__device__ unsigned g_cnt[C_STEPS];                   // zero-init; consumer resets each run

__global__ __launch_bounds__(128, 1)
void cpg_fused(const float* __restrict__ x,
               const float* __restrict__ fc1_w, const float* __restrict__ fc1_b,
               const float* __restrict__ fc2_w, const float* __restrict__ fc2_b,
               const float* __restrict__ fc3_w, const float* __restrict__ fc3_b,
               const float* __restrict__ fcd_w, const float* __restrict__ fcd_b,
               const float* __restrict__ fc4_w, const float* __restrict__ fc4_b,
               const float* __restrict__ enc,  const float* __restrict__ osc_bias,
               const float* __restrict__ dec,
               float* __restrict__ out)
{
    const int tid = threadIdx.x;
    const int bid = blockIdx.x;
    const float x0 = x[0], x1 = x[1];

    if (bid < NBP) {
        // ============================ PRODUCER ============================
        __shared__ float sh_h[128];
        __shared__ float sh_h2[128];
        __shared__ float sh_o[8];

        // warp0: per-neuron constants. 8 lanes/osc, 4 osc/warp, 7 neurons/lane.
        float e0[7], e1[7], bb[7], d0[7], d1[7], w4[7];
        if (tid < 32) {
            const int q   = tid >> 3;            // 0..3 oscillator slot in warp
            const int l8  = tid & 7;
            const int osc = bid * 4 + q;         // global oscillator id (may be >= 50)
            #pragma unroll
            for (int k = 0; k < 7; ++k) {
                int n = l8 + 8 * k;
                if (osc < C_NOSC && n < C_NPER) {
                    int idx = osc * C_NPER + n;
                    e0[k] = enc[idx * 2 + 0];
                    e1[k] = enc[idx * 2 + 1];
                    bb[k] = osc_bias[idx];
                    d0[k] = dec[osc * 2 * C_NPER + n];
                    d1[k] = dec[osc * 2 * C_NPER + C_NPER + n];
                    w4[k] = fc4_w[idx];
                } else {
                    e0[k] = e1[k] = bb[k] = d0[k] = d1[k] = w4[k] = 0.f;
                }
            }
        }

        // h = relu(fc1 x + b1)
        {
            float v = fmaf(fc1_w[tid * 2], x0, fmaf(fc1_w[tid * 2 + 1], x1, fc1_b[tid]));
            sh_h[tid] = fmaxf(v, 0.f);
        }
        __syncthreads();

        // h2 = relu(fc2 h + b2): one row per thread, float4 loads
        {
            const float4* wr = (const float4*)(fc2_w + tid * 128);
            float a0 = 0.f, a1 = 0.f, a2 = 0.f, a3 = 0.f;
            #pragma unroll 8
            for (int j = 0; j < 32; ++j) {
                float4 w = wr[j];
                a0 = fmaf(w.x, sh_h[4 * j + 0], a0);
                a1 = fmaf(w.y, sh_h[4 * j + 1], a1);
                a2 = fmaf(w.z, sh_h[4 * j + 2], a2);
                a3 = fmaf(w.w, sh_h[4 * j + 3], a3);
            }
            sh_h2[tid] = fmaxf((a0 + a1) + (a2 + a3) + fc2_b[tid], 0.f);
        }
        __syncthreads();

        // warp1: this block's 8 fc3 rows -> o0 (rows bid*8 .. bid*8+7, guard < 100)
        if (tid >= 32 && tid < 64) {
            const int r     = (tid - 32) >> 2;       // 0..7
            const int lane4 = tid & 3;
            const int row   = bid * 8 + r;
            float s = 0.f;
            if (row < 2 * C_NOSC) {
                const float* wr = fc3_w + row * 128 + lane4 * 32;
                const float* hv = sh_h2 + lane4 * 32;
                #pragma unroll 8
                for (int k = 0; k < 32; ++k) s = fmaf(wr[k], hv[k], s);
            }
            s += __shfl_down_sync(0xffffffffu, s, 2, 4);
            s += __shfl_down_sync(0xffffffffu, s, 1, 4);
            if (lane4 == 0) sh_o[r] = (row < 2 * C_NOSC) ? s + fc3_b[row] : 0.f;
        }
        __syncthreads();

        // warp0: 100-step recurrence. 3-level butterfly (width 8) on the critical path.
        if (tid < 32) {
            const int q = tid >> 3;
            float s0 = sh_o[2 * q];
            float s1 = sh_o[2 * q + 1];
            float* tq_slot = g_tq + bid;
            unsigned* cnt  = g_cnt;

            for (int s = 0; s < C_STEPS; ++s) {
                float a0 = 0.f, a1 = 0.f, at = 0.f;
                #pragma unroll
                for (int k = 0; k < 7; ++k) {
                    float a = fmaxf(fmaf(e0[k], s0, fmaf(e1[k], s1, bb[k])), 0.f);
                    a0 = fmaf(d0[k], a, a0);
                    a1 = fmaf(d1[k], a, a1);
                    at = fmaf(w4[k], a, at);
                }
                // width-8 butterfly for the recurrence values
                #pragma unroll
                for (int off = 1; off < 8; off <<= 1) {
                    a0 += __shfl_xor_sync(0xffffffffu, a0, off, 8);
                    a1 += __shfl_xor_sync(0xffffffffu, a1, off, 8);
                }
                s0 = fmaf(C_DT, a0, s0);
                s1 = fmaf(C_DT, a1, s1);

                // full-warp torque partial (4 oscillators) — off the recurrence path
                #pragma unroll
                for (int off = 1; off < 32; off <<= 1)
                    at += __shfl_xor_sync(0xffffffffu, at, off);

                if (tid == 0) {
                    tq_slot[s * 32] = at;                       // plain store ...
                    asm volatile("red.release.gpu.global.add.u32 [%0], %1;"
                                 :: "l"(cnt + s), "r"(1u) : "memory");  // ... published by release
                }
            }
        }
    } else {
        // ============================ CONSUMER ============================
        __shared__ float sh_h[128];
        __shared__ float sh_direct;
        __shared__ float sh_torque[C_STEPS];
        __shared__ volatile int sh_ready[C_STEPS];
        __shared__ float sh_l[2 * C_STEPS];

        if (tid < C_STEPS) sh_ready[tid] = 0;

        // h = relu(fc1 x + b1), then direct = fcd.h + fcd_b + fc4_b
        {
            float v = fmaf(fc1_w[tid * 2], x0, fmaf(fc1_w[tid * 2 + 1], x1, fc1_b[tid]));
            sh_h[tid] = fmaxf(v, 0.f);
        }
        __syncthreads();
        if (tid < 32) {
            float s = 0.f;
            #pragma unroll
            for (int k = 0; k < 4; ++k)
                s = fmaf(fcd_w[tid + 32 * k], sh_h[tid + 32 * k], s);
            #pragma unroll
            for (int off = 16; off; off >>= 1)
                s += __shfl_down_sync(0xffffffffu, s, off);
            if (tid == 0) sh_direct = s + fcd_b[0] + fc4_b[0];
        }
        __syncthreads();
        const float direct = sh_direct;

        // threads 0..99: wait for step tid's 13 partials, reduce, publish to smem
        if (tid < C_STEPS) {
            const unsigned* cp = g_cnt + tid;
            unsigned c;
            do {
                asm volatile("ld.acquire.gpu.global.u32 %0, [%1];" : "=r"(c) : "l"(cp));
            } while (c < NBP);
            const float4* row = (const float4*)(g_tq + tid * 32);
            float4 q0 = row[0], q1 = row[1], q2 = row[2];
            float t = ((q0.x + q0.y) + (q0.z + q0.w))
                    + ((q1.x + q1.y) + (q1.z + q1.w))
                    + ((q2.x + q2.y) + (q2.z + q2.w))
                    + g_tq[tid * 32 + 12];
            sh_torque[tid] = t + direct;
            __threadfence_block();
            sh_ready[tid] = 1;
        }

        // one trailing lane integrates the limb as torques become ready
        if (tid == 127) {
            volatile float* vtq = sh_torque;
            float th = x0, om = 0.f;
            for (int t = 0; t < C_STEPS; ++t) {
                while (!sh_ready[t]) { }
                float torque = vtq[t];
                float th2 = fmaf(C_DT, om, th);
                float om2 = fmaf(C_DT, torque - C_MGL2 * __sinf(th), om);
                bool hit = (th2 > C_LIM) || (th2 < -C_LIM);
                th2 = fminf(fmaxf(th2, -C_LIM), C_LIM);
                om2 = hit ? 0.f : om2;
                sh_l[2 * t]     = th2;
                sh_l[2 * t + 1] = om2;
                th = th2; om = om2;
            }
        }
        __syncthreads();

        // reset counters for the next graph replay (all producers already done)
        if (tid < C_STEPS) g_cnt[tid] = 0;

        // race-free coalesced output: out[0..199]=l_states, out[200..299]=torques
        out[tid] = sh_l[tid];
        if (tid < 72)  out[128 + tid] = sh_l[128 + tid];
        if (tid < 100) out[200 + tid] = sh_torque[tid];
    }
}

extern "C" void kernel_launch(void* const* d_in, const int* in_sizes, int n_in,
                              void* d_out, int out_size) {
    const float* x        = (const float*)d_in[0];
    const float* fc1_w    = (const float*)d_in[1];
    const float* fc1_b    = (const float*)d_in[2];
    const float* fc2_w    = (const float*)d_in[3];
    const float* fc2_b    = (const float*)d_in[4];
    const float* fc3_w    = (const float*)d_in[5];
    const float* fc3_b    = (const float*)d_in[6];
    const float* fcd_w    = (const float*)d_in[7];
    const float* fcd_b    = (const float*)d_in[8];
    const float* fc4_w    = (const float*)d_in[9];
    const float* fc4_b    = (const float*)d_in[10];
    const float* enc      = (const float*)d_in[11];
    const float* osc_bias = (const float*)d_in[12];
    const float* dec      = (const float*)d_in[13];
    float* out = (float*)d_out;

    cpg_fused<<<NBP + 1, 128>>>(x, fc1_w, fc1_b, fc2_w, fc2_b, fc3_w, fc3_b,
                                fcd_w, fcd_b, fc4_w, fc4_b, enc, osc_bias, dec, out);
}

// round 7
// speedup vs baseline: 2.8156x; 2.8156x over previous
#include <cuda_runtime.h>
#include <math.h>

#define C_DT    0.01f
#define C_STEPS 100
#define C_NOSC  50
#define C_NPER  50
#define C_LIM   1.0471975511965976f   /* pi/3 */
#define C_MGL2  4.905f                /* m*g*(l/2), I = 1 */
#define NBP     13                    /* producer blocks: 4 oscillators each (52, 2 padded) */

__device__ __align__(128) float g_tq[C_STEPS * 64];  // [step][osc-group 0..51, padded 64]
__device__ unsigned g_done = 0;                       // consumer resets each run

__global__ __launch_bounds__(128, 1)
void cpg_fused(const float* __restrict__ x,
               const float* __restrict__ fc1_w, const float* __restrict__ fc1_b,
               const float* __restrict__ fc2_w, const float* __restrict__ fc2_b,
               const float* __restrict__ fc3_w, const float* __restrict__ fc3_b,
               const float* __restrict__ fcd_w, const float* __restrict__ fcd_b,
               const float* __restrict__ fc4_w, const float* __restrict__ fc4_b,
               const float* __restrict__ enc,  const float* __restrict__ osc_bias,
               const float* __restrict__ dec,
               float* __restrict__ out)
{
    const int tid = threadIdx.x;
    const int bid = blockIdx.x;
    const float x0 = x[0], x1 = x[1];

    if (bid < NBP) {
        // ============================ PRODUCER ============================
        __shared__ float sh_h[128];
        __shared__ float sh_h2[128];
        __shared__ float sh_o[8];

        // warp0: per-neuron constants. 8 lanes/osc, 4 osc/warp, 7 neurons/lane.
        float e0[7], e1[7], bb[7], d0[7], d1[7], w4[7];
        if (tid < 32) {
            const int q   = tid >> 3;            // oscillator slot in warp (0..3)
            const int l8  = tid & 7;
            const int osc = bid * 4 + q;         // global oscillator id (may be >= 50)
            #pragma unroll
            for (int k = 0; k < 7; ++k) {
                int n = l8 + 8 * k;
                if (osc < C_NOSC && n < C_NPER) {
                    int idx = osc * C_NPER + n;
                    e0[k] = enc[idx * 2 + 0];
                    e1[k] = enc[idx * 2 + 1];
                    bb[k] = osc_bias[idx];
                    d0[k] = dec[osc * 2 * C_NPER + n];
                    d1[k] = dec[osc * 2 * C_NPER + C_NPER + n];
                    w4[k] = fc4_w[idx];
                } else {
                    e0[k] = e1[k] = bb[k] = d0[k] = d1[k] = w4[k] = 0.f;
                }
            }
        }

        // h = relu(fc1 x + b1)
        {
            float v = fmaf(fc1_w[tid * 2], x0, fmaf(fc1_w[tid * 2 + 1], x1, fc1_b[tid]));
            sh_h[tid] = fmaxf(v, 0.f);
        }
        __syncthreads();

        // h2 = relu(fc2 h + b2): one row per thread, float4 loads
        {
            const float4* wr = (const float4*)(fc2_w + tid * 128);
            float a0 = 0.f, a1 = 0.f, a2 = 0.f, a3 = 0.f;
            #pragma unroll 8
            for (int j = 0; j < 32; ++j) {
                float4 w = wr[j];
                a0 = fmaf(w.x, sh_h[4 * j + 0], a0);
                a1 = fmaf(w.y, sh_h[4 * j + 1], a1);
                a2 = fmaf(w.z, sh_h[4 * j + 2], a2);
                a3 = fmaf(w.w, sh_h[4 * j + 3], a3);
            }
            sh_h2[tid] = fmaxf((a0 + a1) + (a2 + a3) + fc2_b[tid], 0.f);
        }
        __syncthreads();

        // warp1: this block's 8 fc3 rows -> o0 (guard row < 100)
        if (tid >= 32 && tid < 64) {
            const int r     = (tid - 32) >> 2;       // 0..7
            const int lane4 = tid & 3;
            const int row   = bid * 8 + r;
            float s = 0.f;
            if (row < 2 * C_NOSC) {
                const float* wr = fc3_w + row * 128 + lane4 * 32;
                const float* hv = sh_h2 + lane4 * 32;
                #pragma unroll 8
                for (int k = 0; k < 32; ++k) s = fmaf(wr[k], hv[k], s);
            }
            s += __shfl_down_sync(0xffffffffu, s, 2, 4);
            s += __shfl_down_sync(0xffffffffu, s, 1, 4);
            if (lane4 == 0) sh_o[r] = (row < 2 * C_NOSC) ? s + fc3_b[row] : 0.f;
        }
        __syncthreads();

        // warp0: 100-step recurrence. 3-level butterfly (width 8) on the path.
        // Torque partial: lane l8==0 of each group stores directly — NO extra shfls.
        if (tid < 32) {
            const int q  = tid >> 3;
            const int l8 = tid & 7;
            float s0 = sh_o[2 * q];
            float s1 = sh_o[2 * q + 1];
            float* tq_slot = g_tq + bid * 4 + q;

            for (int s = 0; s < C_STEPS; ++s) {
                float a0 = 0.f, a1 = 0.f, at = 0.f;
                #pragma unroll
                for (int k = 0; k < 7; ++k) {
                    float a = fmaxf(fmaf(e0[k], s0, fmaf(e1[k], s1, bb[k])), 0.f);
                    a0 = fmaf(d0[k], a, a0);
                    a1 = fmaf(d1[k], a, a1);
                    at = fmaf(w4[k], a, at);
                }
                #pragma unroll
                for (int off = 1; off < 8; off <<= 1) {
                    a0 += __shfl_xor_sync(0xffffffffu, a0, off, 8);
                    a1 += __shfl_xor_sync(0xffffffffu, a1, off, 8);
                    at += __shfl_xor_sync(0xffffffffu, at, off, 8);
                }
                s0 = fmaf(C_DT, a0, s0);
                s1 = fmaf(C_DT, a1, s1);
                if (l8 == 0) tq_slot[s * 64] = at;   // plain STG, off critical path
            }
        }
        __syncthreads();
        if (tid == 0) {
            __threadfence();                 // publish all torque stores ...
            atomicAdd(&g_done, 1u);          // ... then signal (release pattern)
        }
    } else {
        // ============================ CONSUMER ============================
        __shared__ float sh_h[128];
        __shared__ float sh_direct;
        __shared__ float sh_torque[C_STEPS];
        __shared__ float sh_l[2 * C_STEPS];

        // overlap with producers: h = relu(fc1 x + b1), direct = fcd.h + biases
        {
            float v = fmaf(fc1_w[tid * 2], x0, fmaf(fc1_w[tid * 2 + 1], x1, fc1_b[tid]));
            sh_h[tid] = fmaxf(v, 0.f);
        }
        __syncthreads();
        if (tid < 32) {
            float s = 0.f;
            #pragma unroll
            for (int k = 0; k < 4; ++k)
                s = fmaf(fcd_w[tid + 32 * k], sh_h[tid + 32 * k], s);
            #pragma unroll
            for (int off = 16; off; off >>= 1)
                s += __shfl_down_sync(0xffffffffu, s, off);
            if (tid == 0) sh_direct = s + fcd_b[0] + fc4_b[0];
        }

        // single-thread low-pressure poll: one line, read-only, nanosleep backoff
        if (tid == 0) {
            unsigned c;
            const unsigned* dp = &g_done;
            do {
                asm volatile("ld.acquire.gpu.global.u32 %0, [%1];" : "=r"(c) : "l"(dp));
                if (c < NBP) __nanosleep(64);
            } while (c < NBP);
            g_done = 0;                      // reset for next graph replay
        }
        __syncthreads();

        // 100 threads: reduce 52 group partials per step
        if (tid < C_STEPS) {
            const float4* row = (const float4*)(g_tq + tid * 64);
            float t = 0.f;
            #pragma unroll
            for (int j = 0; j < 13; ++j) {
                float4 v = row[j];
                t += (v.x + v.y) + (v.z + v.w);
            }
            sh_torque[tid] = t + sh_direct;
        }
        __syncthreads();

        // serial limb integration
        if (tid == 0) {
            float th = x0, om = 0.f;
            #pragma unroll 4
            for (int t = 0; t < C_STEPS; ++t) {
                float torque = sh_torque[t];
                float th2 = fmaf(C_DT, om, th);
                float om2 = fmaf(C_DT, torque - C_MGL2 * __sinf(th), om);
                bool hit = (th2 > C_LIM) || (th2 < -C_LIM);
                th2 = fminf(fmaxf(th2, -C_LIM), C_LIM);
                om2 = hit ? 0.f : om2;
                sh_l[2 * t]     = th2;
                sh_l[2 * t + 1] = om2;
                th = th2; om = om2;
            }
        }
        __syncthreads();

        // race-free coalesced output: out[0..199]=l_states, out[200..299]=torques
        out[tid] = sh_l[tid];
        if (tid < 72)  out[128 + tid] = sh_l[128 + tid];
        if (tid < 100) out[200 + tid] = sh_torque[tid];
    }
}

extern "C" void kernel_launch(void* const* d_in, const int* in_sizes, int n_in,
                              void* d_out, int out_size) {
    const float* x        = (const float*)d_in[0];
    const float* fc1_w    = (const float*)d_in[1];
    const float* fc1_b    = (const float*)d_in[2];
    const float* fc2_w    = (const float*)d_in[3];
    const float* fc2_b    = (const float*)d_in[4];
    const float* fc3_w    = (const float*)d_in[5];
    const float* fc3_b    = (const float*)d_in[6];
    const float* fcd_w    = (const float*)d_in[7];
    const float* fcd_b    = (const float*)d_in[8];
    const float* fc4_w    = (const float*)d_in[9];
    const float* fc4_b    = (const float*)d_in[10];
    const float* enc      = (const float*)d_in[11];
    const float* osc_bias = (const float*)d_in[12];
    const float* dec      = (const float*)d_in[13];
    float* out = (float*)d_out;

    cpg_fused<<<NBP + 1, 128>>>(x, fc1_w, fc1_b, fc2_w, fc2_b, fc3_w, fc3_b,
                                fcd_w, fcd_b, fc4_w, fc4_b, enc, osc_bias, dec, out);
}